// round 11
// baseline (speedup 1.0000x reference)
#include <cuda_runtime.h>
#include <cuda_bf16.h>
#include <math.h>
#include <stdint.h>

#define N_NODES 50000
#define N_EDGES 800000
#define H 128
#define ED 16
#define NG 64
#define NC 10
#define FULLMASK 0xffffffffu
#define NP1 (N_NODES + 1)
#define SCAN_BLOCKS ((NP1 + 1023) / 1024)

// ---------------- scratch (device globals; no allocation allowed) ----------------
__device__ __nv_bfloat16 g_zbf[(size_t)N_NODES * H];   // GEMM output, bf16 messages
__device__ float g_hA[(size_t)N_NODES * H];
__device__ float g_hB[(size_t)N_NODES * H];
__device__ __nv_bfloat16 g_xbf[(size_t)N_NODES * H];
__device__ __nv_bfloat16 g_hbfA[(size_t)N_NODES * H];
__device__ __nv_bfloat16 g_hbfB[(size_t)N_NODES * H];
__device__ __nv_bfloat16 g_Wt[3 * H * H];     // per-layer W transposed [n][k], bf16
__device__ float g_ssrc[N_NODES];
__device__ float g_sdst[N_NODES];
__device__ float g_att[N_NODES];
__device__ float g_eproj[3][N_EDGES];
__device__ int   g_rowptr[NP1];
__device__ int   g_cursor[N_NODES];
__device__ int   g_bsum[SCAN_BLOCKS];
__device__ int   g_csr_src[N_EDGES];
__device__ int   g_gstart[NG + 1];
__device__ float g_hg[NG * 3 * H];

// ---------------- convert x -> bf16 and W1/2/3 -> transposed bf16 ----------------
#define CONV_XBLOCKS ((N_NODES * H) / 1024)   // 6250
__global__ void k_conv(const float* __restrict__ x, const float* __restrict__ W1,
                       const float* __restrict__ W2, const float* __restrict__ W3) {
    int b = blockIdx.x;
    if (b < CONV_XBLOCKS) {
        int i = (b * 256 + threadIdx.x) * 4;
        float4 v = *(const float4*)(x + i);
        __nv_bfloat162 p0 = __floats2bfloat162_rn(v.x, v.y);
        __nv_bfloat162 p1 = __floats2bfloat162_rn(v.z, v.w);
        uint2 u; u.x = *(uint32_t*)&p0; u.y = *(uint32_t*)&p1;
        *(uint2*)&g_xbf[i] = u;
    } else {
        int idx = ((b - CONV_XBLOCKS) * 256 + threadIdx.x) * 4;
        if (idx < 3 * H * H) {
            int l = idx >> 14;
            int rem = idx & (H * H - 1);
            int n = rem >> 7, k = rem & 127;
            const float* Wsrc = (l == 0) ? W1 : (l == 1) ? W2 : W3;
            float f0 = Wsrc[(k + 0) * H + n];
            float f1 = Wsrc[(k + 1) * H + n];
            float f2 = Wsrc[(k + 2) * H + n];
            float f3 = Wsrc[(k + 3) * H + n];
            __nv_bfloat162 p0 = __floats2bfloat162_rn(f0, f1);
            __nv_bfloat162 p1 = __floats2bfloat162_rn(f2, f3);
            uint2 u; u.x = *(uint32_t*)&p0; u.y = *(uint32_t*)&p1;
            *(uint2*)&g_Wt[idx] = u;
        }
    }
}

// ---------------- init: zero counts + hg, graph segment starts ----------------
__global__ void k_init(const int* __restrict__ gid) {
    int i = blockIdx.x * blockDim.x + threadIdx.x;
    if (i < NP1) g_rowptr[i] = 0;
    if (i < NG * 3 * H) g_hg[i] = 0.f;
    if (i < N_NODES) {
        int gi = gid[i];
        int gp = (i == 0) ? -1 : gid[i - 1];
        for (int g = gp + 1; g <= gi; g++) g_gstart[g] = i;
        if (i == N_NODES - 1)
            for (int g = gi + 1; g <= NG; g++) g_gstart[g] = N_NODES;
    }
}

__global__ void k_hist(const int* __restrict__ dst) {
    int e = blockIdx.x * blockDim.x + threadIdx.x;
    if (e < N_EDGES) atomicAdd(&g_rowptr[dst[e] + 1], 1);
}

// ---------------- scan phase 1: block-local inclusive ----------------
__global__ void k_scan1() {
    __shared__ int wsum[32];
    int tid = threadIdx.x, lane = tid & 31, wid = tid >> 5;
    int i = blockIdx.x * 1024 + tid;
    int x = (i < NP1) ? g_rowptr[i] : 0;
#pragma unroll
    for (int off = 1; off < 32; off <<= 1) {
        int t = __shfl_up_sync(FULLMASK, x, off);
        if (lane >= off) x += t;
    }
    if (lane == 31) wsum[wid] = x;
    __syncthreads();
    if (wid == 0) {
        int y = wsum[lane];
#pragma unroll
        for (int off = 1; off < 32; off <<= 1) {
            int t = __shfl_up_sync(FULLMASK, y, off);
            if (lane >= off) y += t;
        }
        wsum[lane] = y;
    }
    __syncthreads();
    int v = x + (wid ? wsum[wid - 1] : 0);
    if (i < NP1) g_rowptr[i] = v;
    if (tid == 1023) g_bsum[blockIdx.x] = v;
}

// ---------------- scan phase 2 (fused, parallel): add block offsets + cursor ----------------
__global__ void k_scan3() {
    __shared__ int warpsum[2];
    int b = blockIdx.x;
    int lim = b >> 2;
    int tid = threadIdx.x;
    int v = 0;
    if (tid < lim) v = g_bsum[tid];
    if (tid < 64) {
#pragma unroll
        for (int off = 16; off >= 1; off >>= 1)
            v += __shfl_xor_sync(FULLMASK, v, off);
        if ((tid & 31) == 0) warpsum[tid >> 5] = v;
    }
    __syncthreads();
    int soff = warpsum[0] + warpsum[1];
    int i = b * 256 + tid;
    if (i < NP1) {
        int vv = g_rowptr[i] + soff;
        g_rowptr[i] = vv;
        if (i < N_NODES) g_cursor[i] = vv;
    }
}

// ---------------- scatter: CSR src + per-layer edge projections ----------------
__global__ void k_scatter(const int* __restrict__ src, const int* __restrict__ dst,
                          const float* __restrict__ e_feat,
                          const float* __restrict__ a1, const float* __restrict__ a2,
                          const float* __restrict__ a3) {
    int e = blockIdx.x * blockDim.x + threadIdx.x;
    if (e >= N_EDGES) return;
    int d = dst[e];
    int p = atomicAdd(&g_cursor[d], 1);
    g_csr_src[p] = src[e];
    const float* ef = e_feat + (size_t)e * ED;
    float p1 = 0.f, p2 = 0.f, p3 = 0.f;
#pragma unroll
    for (int i = 0; i < 4; i++) {
        float4 f = *(const float4*)(ef + i * 4);
        float4 u = *(const float4*)(a1 + 2 * H + i * 4);
        float4 v = *(const float4*)(a2 + 2 * H + i * 4);
        float4 w = *(const float4*)(a3 + 2 * H + i * 4);
        p1 += f.x * u.x + f.y * u.y + f.z * u.z + f.w * u.w;
        p2 += f.x * v.x + f.y * v.y + f.z * v.z + f.w * v.w;
        p3 += f.x * w.x + f.y * w.y + f.z * w.z + f.w * w.w;
    }
    g_eproj[0][p] = p1;
    g_eproj[1][p] = p2;
    g_eproj[2][p] = p3;
}

// ---------------- pipelined bf16 GEMM + fused attention-score epilogue ----------------
__device__ __forceinline__ void mma_bf16(float* c, const uint32_t* a, const uint32_t* b) {
    asm volatile(
        "mma.sync.aligned.m16n8k16.row.col.f32.bf16.bf16.f32 "
        "{%0,%1,%2,%3}, {%4,%5,%6,%7}, {%8,%9}, {%0,%1,%2,%3};"
        : "+f"(c[0]), "+f"(c[1]), "+f"(c[2]), "+f"(c[3])
        : "r"(a[0]), "r"(a[1]), "r"(a[2]), "r"(a[3]), "r"(b[0]), "r"(b[1]));
}
__device__ __forceinline__ void cp16(uint32_t dst, const void* src, bool full) {
    int sz = full ? 16 : 0;
    asm volatile("cp.async.cg.shared.global [%0], [%1], 16, %2;\n"
                 :: "r"(dst), "l"(src), "r"(sz));
}

#define BSTRIDE 40
#define ATILE (128 * BSTRIDE)
#define WTILE (128 * BSTRIDE)
#define GEMM_SMEM ((4 * ATILE) * 2 + 256 * 4)   // ~42 KB

__global__ void __launch_bounds__(256, 2)
k_gemm_tc(const __nv_bfloat16* __restrict__ A, const __nv_bfloat16* __restrict__ Wt,
          const float* __restrict__ avec, __nv_bfloat16* __restrict__ Zbf, int nrows) {
    extern __shared__ __nv_bfloat16 smb[];
    __nv_bfloat16* As = smb;                    // [2][128][40]
    __nv_bfloat16* Ws = smb + 2 * ATILE;        // [2][128][40]
    float* red = (float*)(smb + 4 * ATILE);     // [128][2]

    int tid = threadIdx.x;
    int wid = tid >> 5, lane = tid & 31;
    int gId = lane >> 2, tig = lane & 3;
    int m0 = blockIdx.x * 128;
    int wm = (wid >> 1) * 32;
    int wn = (wid & 1) * 64;

    uint32_t sA = (uint32_t)__cvta_generic_to_shared(As);
    uint32_t sW = (uint32_t)__cvta_generic_to_shared(Ws);

    if (tid < 128) { red[tid * 2] = 0.f; red[tid * 2 + 1] = 0.f; }

    float acc[2][8][4];
#pragma unroll
    for (int i = 0; i < 2; i++)
#pragma unroll
        for (int j = 0; j < 8; j++)
#pragma unroll
            for (int k = 0; k < 4; k++) acc[i][j][k] = 0.f;

    auto load_stage = [&](int kt, int buf) {
#pragma unroll
        for (int p = 0; p < 2; p++) {
            int idx = p * 256 + tid;
            int m  = idx >> 2;
            int c8 = (idx & 3) * 8;
            bool v = (m0 + m) < nrows;
            cp16(sA + (uint32_t)(buf * ATILE + m * BSTRIDE + c8) * 2,
                 A + (size_t)(v ? (m0 + m) : 0) * H + kt + c8, v);
        }
#pragma unroll
        for (int p = 0; p < 2; p++) {
            int idx = p * 256 + tid;
            int n  = idx >> 2;
            int c8 = (idx & 3) * 8;
            cp16(sW + (uint32_t)(buf * WTILE + n * BSTRIDE + c8) * 2,
                 Wt + (size_t)n * H + kt + c8, true);
        }
        asm volatile("cp.async.commit_group;\n");
    };

    load_stage(0, 0);

#pragma unroll
    for (int t = 0; t < 4; t++) {
        if (t < 3) {
            load_stage((t + 1) * 32, (t + 1) & 1);
            asm volatile("cp.async.wait_group 1;\n");
        } else {
            asm volatile("cp.async.wait_group 0;\n");
        }
        __syncthreads();
        int buf = t & 1;
        const __nv_bfloat16* Ab = As + buf * ATILE;
        const __nv_bfloat16* Wb = Ws + buf * WTILE;
#pragma unroll
        for (int ks = 0; ks < 32; ks += 16) {
            uint32_t a[2][4], b[8][2];
#pragma unroll
            for (int mi = 0; mi < 2; mi++) {
                int r = wm + mi * 16;
                a[mi][0] = *(const uint32_t*)&Ab[(r + gId) * BSTRIDE + ks + 2 * tig];
                a[mi][1] = *(const uint32_t*)&Ab[(r + gId + 8) * BSTRIDE + ks + 2 * tig];
                a[mi][2] = *(const uint32_t*)&Ab[(r + gId) * BSTRIDE + ks + 2 * tig + 8];
                a[mi][3] = *(const uint32_t*)&Ab[(r + gId + 8) * BSTRIDE + ks + 2 * tig + 8];
            }
#pragma unroll
            for (int ni = 0; ni < 8; ni++) {
                int n = wn + ni * 8 + gId;
                b[ni][0] = *(const uint32_t*)&Wb[n * BSTRIDE + ks + 2 * tig];
                b[ni][1] = *(const uint32_t*)&Wb[n * BSTRIDE + ks + 2 * tig + 8];
            }
#pragma unroll
            for (int mi = 0; mi < 2; mi++)
#pragma unroll
                for (int ni = 0; ni < 8; ni++)
                    mma_bf16(acc[mi][ni], a[mi], b[ni]);
        }
        __syncthreads();
    }

    // epilogue: bf16 z store + attention-score partial dots (fp32)
#pragma unroll
    for (int mi = 0; mi < 2; mi++) {
        float ps0 = 0.f, pd0 = 0.f, ps1 = 0.f, pd1 = 0.f;
        int rl = wm + mi * 16 + gId;
        int r0 = m0 + rl;
#pragma unroll
        for (int ni = 0; ni < 8; ni++) {
            int c = wn + ni * 8 + tig * 2;
            float a0s = avec[c], a1s = avec[c + 1];
            float a0d = avec[H + c], a1d = avec[H + c + 1];
            ps0 += acc[mi][ni][0] * a0s + acc[mi][ni][1] * a1s;
            pd0 += acc[mi][ni][0] * a0d + acc[mi][ni][1] * a1d;
            ps1 += acc[mi][ni][2] * a0s + acc[mi][ni][3] * a1s;
            pd1 += acc[mi][ni][2] * a0d + acc[mi][ni][3] * a1d;
            if (r0 < nrows) {
                __nv_bfloat162 p = __floats2bfloat162_rn(acc[mi][ni][0], acc[mi][ni][1]);
                *(uint32_t*)&Zbf[(size_t)r0 * H + c] = *(uint32_t*)&p;
            }
            if (r0 + 8 < nrows) {
                __nv_bfloat162 p = __floats2bfloat162_rn(acc[mi][ni][2], acc[mi][ni][3]);
                *(uint32_t*)&Zbf[(size_t)(r0 + 8) * H + c] = *(uint32_t*)&p;
            }
        }
        atomicAdd(&red[rl * 2],     ps0);
        atomicAdd(&red[rl * 2 + 1], pd0);
        atomicAdd(&red[(rl + 8) * 2],     ps1);
        atomicAdd(&red[(rl + 8) * 2 + 1], pd1);
    }
    __syncthreads();
    if (tid < 128 && m0 + tid < nrows) {
        g_ssrc[m0 + tid] = red[tid * 2];
        g_sdst[m0 + tid] = red[tid * 2 + 1];
    }
}

// ---------------- warp-per-node single-pass softmax + aggregation (bf16 gather) ----------------
__global__ void k_aggregate(const float* __restrict__ eproj, float* __restrict__ h_out,
                            __nv_bfloat16* __restrict__ hbf,
                            const float* __restrict__ w_att, const float* __restrict__ b_att) {
    int t = blockIdx.x * blockDim.x + threadIdx.x;
    int w = t >> 5, lane = t & 31;
    if (w >= N_NODES) return;
    int s0 = g_rowptr[w], s1 = g_rowptr[w + 1];
    float sd = g_sdst[w];

    float ax = 0.f, ay = 0.f, az = 0.f, aw = 0.f;
    float ssum = 0.f;
    for (int base = s0; base < s1; base += 32) {
        int e = base + lane;
        float ex = 0.f;
        int sj = 0;
        if (e < s1) {
            sj = g_csr_src[e];
            float tt = g_ssrc[sj] + sd + eproj[e];
            tt = (tt >= 0.f) ? tt : 0.2f * tt;
            ex = __expf(tt);
        }
        ssum += ex;
        int cnt = min(32, s1 - base);
        if (cnt == 32) {
#pragma unroll 8
            for (int j = 0; j < 32; j++) {
                float exj = __shfl_sync(FULLMASK, ex, j);
                int   srj = __shfl_sync(FULLMASK, sj, j);
                uint2 u = *(const uint2*)&g_zbf[(size_t)srj * H + lane * 4];
                float2 f0 = __bfloat1622float2(*(__nv_bfloat162*)&u.x);
                float2 f1 = __bfloat1622float2(*(__nv_bfloat162*)&u.y);
                ax += exj * f0.x; ay += exj * f0.y;
                az += exj * f1.x; aw += exj * f1.y;
            }
        } else {
            for (int j = 0; j < cnt; j++) {
                float exj = __shfl_sync(FULLMASK, ex, j);
                int   srj = __shfl_sync(FULLMASK, sj, j);
                uint2 u = *(const uint2*)&g_zbf[(size_t)srj * H + lane * 4];
                float2 f0 = __bfloat1622float2(*(__nv_bfloat162*)&u.x);
                float2 f1 = __bfloat1622float2(*(__nv_bfloat162*)&u.y);
                ax += exj * f0.x; ay += exj * f0.y;
                az += exj * f1.x; aw += exj * f1.y;
            }
        }
    }
#pragma unroll
    for (int off = 16; off >= 1; off >>= 1)
        ssum += __shfl_xor_sync(FULLMASK, ssum, off);
    float inv = (ssum > 0.f) ? 1.f / ssum : 0.f;

    float4 o;
    o.x = fmaxf(ax * inv, 0.f);
    o.y = fmaxf(ay * inv, 0.f);
    o.z = fmaxf(az * inv, 0.f);
    o.w = fmaxf(aw * inv, 0.f);
    *(float4*)&h_out[(size_t)w * H + lane * 4] = o;
    if (hbf) {
        __nv_bfloat162 p0 = __floats2bfloat162_rn(o.x, o.y);
        __nv_bfloat162 p1 = __floats2bfloat162_rn(o.z, o.w);
        uint2 u; u.x = *(uint32_t*)&p0; u.y = *(uint32_t*)&p1;
        *(uint2*)&hbf[(size_t)w * H + lane * 4] = u;
    }

    float4 wa = *(const float4*)&w_att[lane * 4];
    float p = o.x * wa.x + o.y * wa.y + o.z * wa.z + o.w * wa.w;
#pragma unroll
    for (int off = 16; off >= 1; off >>= 1)
        p += __shfl_xor_sync(FULLMASK, p, off);
    if (lane == 0) {
        float tt = p + b_att[0];
        tt = (tt >= 0.f) ? tt : 0.01f * tt;
        g_att[w] = __expf(tt);
    }
}

// ---------------- per-graph readout (4-way split, atomic numerators) ----------------
__global__ void k_readout(const float* __restrict__ hsrc, int layer_off) {
    int g = blockIdx.x;
    int q = blockIdx.y;
    int c = threadIdx.x;
    int s = g_gstart[g], e = g_gstart[g + 1];
    float a0 = 0.f;
    for (int i = s + q; i < e; i += 4)
        a0 += g_att[i] * hsrc[(size_t)i * H + c];
    atomicAdd(&g_hg[g * (3 * H) + layer_off + c], a0);
}

// ---------------- classifier + log_softmax ----------------
__global__ void k_cls(const float* __restrict__ Wcls, const float* __restrict__ bcls,
                      float* __restrict__ out) {
    int t = blockIdx.x * blockDim.x + threadIdx.x;
    int w = t >> 5, lane = t & 31;
    if (w >= NG) return;
    int cnt = g_gstart[w + 1] - g_gstart[w];
    float invden = 1.f / (float)(cnt > 1 ? cnt : 1);
    float y = -INFINITY;
    if (lane < NC) {
        float acc = 0.f;
        const float* hgp = &g_hg[w * 3 * H];
#pragma unroll 8
        for (int k = 0; k < 3 * H; k++)
            acc += hgp[k] * Wcls[k * NC + lane];
        y = acc * invden + bcls[lane];
    }
    float mx = y;
#pragma unroll
    for (int off = 16; off >= 1; off >>= 1)
        mx = fmaxf(mx, __shfl_xor_sync(FULLMASK, mx, off));
    float ex = (lane < NC) ? __expf(y - mx) : 0.f;
    float sm = ex;
#pragma unroll
    for (int off = 16; off >= 1; off >>= 1)
        sm += __shfl_xor_sync(FULLMASK, sm, off);
    if (lane < NC) out[w * NC + lane] = (y - mx) - logf(sm);
}

// ---------------- host orchestration ----------------
static cudaStream_t s2 = nullptr;
static cudaEvent_t evFork, evG1, evA1, evR1, evA2, evR2;

extern "C" void kernel_launch(void* const* d_in, const int* in_sizes, int n_in,
                              void* d_out, int out_size) {
    const float* x      = (const float*)d_in[0];
    const float* e_feat = (const float*)d_in[1];
    const int*   src    = (const int*)d_in[2];
    const int*   dst    = (const int*)d_in[3];
    const int*   gid    = (const int*)d_in[4];
    const float* W1 = (const float*)d_in[5];
    const float* a1 = (const float*)d_in[6];
    const float* W2 = (const float*)d_in[7];
    const float* a2 = (const float*)d_in[8];
    const float* W3 = (const float*)d_in[9];
    const float* a3 = (const float*)d_in[10];
    const float* w_att = (const float*)d_in[11];
    const float* b_att = (const float*)d_in[12];
    const float* Wcls  = (const float*)d_in[13];
    const float* bcls  = (const float*)d_in[14];
    float* out = (float*)d_out;

    if (s2 == nullptr) {
        cudaStreamCreateWithFlags(&s2, cudaStreamNonBlocking);
        cudaEventCreateWithFlags(&evFork, cudaEventDisableTiming);
        cudaEventCreateWithFlags(&evG1,  cudaEventDisableTiming);
        cudaEventCreateWithFlags(&evA1,  cudaEventDisableTiming);
        cudaEventCreateWithFlags(&evR1,  cudaEventDisableTiming);
        cudaEventCreateWithFlags(&evA2,  cudaEventDisableTiming);
        cudaEventCreateWithFlags(&evR2,  cudaEventDisableTiming);
        cudaFuncSetAttribute(k_gemm_tc, cudaFuncAttributeMaxDynamicSharedMemorySize, GEMM_SMEM);
    }

    float *p_hA, *p_hB, *p_ep;
    __nv_bfloat16 *p_zbf, *p_xbf, *p_hbfA, *p_hbfB, *p_Wt;
    cudaGetSymbolAddress((void**)&p_zbf,  g_zbf);
    cudaGetSymbolAddress((void**)&p_hA,   g_hA);
    cudaGetSymbolAddress((void**)&p_hB,   g_hB);
    cudaGetSymbolAddress((void**)&p_ep,   g_eproj);
    cudaGetSymbolAddress((void**)&p_xbf,  g_xbf);
    cudaGetSymbolAddress((void**)&p_hbfA, g_hbfA);
    cudaGetSymbolAddress((void**)&p_hbfB, g_hbfB);
    cudaGetSymbolAddress((void**)&p_Wt,   g_Wt);

    int wb = (N_NODES * 32 + 255) / 256;
    int gb = (N_NODES + 127) / 128;
    dim3 rgrid(NG, 4);

    cudaEventRecord(evFork, 0);
    cudaStreamWaitEvent(s2, evFork, 0);

    k_conv<<<CONV_XBLOCKS + 48, 256, 0, s2>>>(x, W1, W2, W3);                 // #1
    k_init<<<(NP1 + 255) / 256, 256>>>(gid);                                  // #2
    k_hist<<<(N_EDGES + 255) / 256, 256>>>(dst);                              // #3
    k_gemm_tc<<<gb, 256, GEMM_SMEM, s2>>>(p_xbf, p_Wt, a1, p_zbf, N_NODES);   // #4
    cudaEventRecord(evG1, s2);
    k_scan1<<<SCAN_BLOCKS, 1024>>>();                                         // #5
    k_scan3<<<(NP1 + 255) / 256, 256>>>();                                    // #6
    k_scatter<<<(N_EDGES + 255) / 256, 256>>>(src, dst, e_feat, a1, a2, a3);  // #7

    // layer 1
    cudaStreamWaitEvent(0, evG1, 0);
    k_aggregate<<<wb, 256>>>(p_ep + 0 * N_EDGES, p_hA, p_hbfA, w_att, b_att);
    cudaEventRecord(evA1, 0);
    cudaStreamWaitEvent(s2, evA1, 0);
    k_readout<<<rgrid, 128, 0, s2>>>(p_hA, 0);
    cudaEventRecord(evR1, s2);

    // layer 2 (overlaps readout-1)
    k_gemm_tc<<<gb, 256, GEMM_SMEM>>>(p_hbfA, p_Wt + H * H, a2, p_zbf, N_NODES);
    k_aggregate<<<wb, 256>>>(p_ep + 1 * N_EDGES, p_hB, p_hbfB, w_att, b_att);
    cudaEventRecord(evA2, 0);
    cudaStreamWaitEvent(s2, evA2, 0);
    k_readout<<<rgrid, 128, 0, s2>>>(p_hB, H);
    cudaEventRecord(evR2, s2);

    // layer 3 (overlaps readout-2)
    k_gemm_tc<<<gb, 256, GEMM_SMEM>>>(p_hbfB, p_Wt + 2 * H * H, a3, p_zbf, N_NODES);
    k_aggregate<<<wb, 256>>>(p_ep + 2 * N_EDGES, p_hA, (__nv_bfloat16*)nullptr, w_att, b_att);
    k_readout<<<rgrid, 128>>>(p_hA, 2 * H);

    cudaStreamWaitEvent(0, evR1, 0);
    cudaStreamWaitEvent(0, evR2, 0);
    k_cls<<<2, 1024>>>(Wcls, bcls, out);
}

// round 13
// speedup vs baseline: 1.1397x; 1.1397x over previous
#include <cuda_runtime.h>
#include <cuda_bf16.h>
#include <math.h>
#include <stdint.h>

#define N_NODES 50000
#define N_EDGES 800000
#define H 128
#define ED 16
#define NG 64
#define NC 10
#define FULLMASK 0xffffffffu
#define NP1 (N_NODES + 1)
#define SCAN_BLOCKS ((NP1 + 1023) / 1024)

// ---------------- scratch (device globals; no allocation allowed) ----------------
__device__ __nv_bfloat16 g_zbf[(size_t)N_NODES * H];   // GEMM output, bf16 messages
__device__ float g_hA[(size_t)N_NODES * H];
__device__ float g_hB[(size_t)N_NODES * H];
__device__ __nv_bfloat16 g_xbf[(size_t)N_NODES * H];
__device__ __nv_bfloat16 g_hbfA[(size_t)N_NODES * H];
__device__ __nv_bfloat16 g_hbfB[(size_t)N_NODES * H];
__device__ __nv_bfloat16 g_Wt[3 * H * H];     // per-layer W transposed [n][k], bf16
__device__ float g_ssrc[N_NODES];
__device__ float g_sdst[N_NODES];
__device__ float g_att[N_NODES];
__device__ float g_eproj[3][N_EDGES];
__device__ int   g_rowptr[NP1];
__device__ int   g_cursor[N_NODES];
__device__ int   g_bsum[SCAN_BLOCKS];
__device__ int   g_csr_src[N_EDGES];
__device__ int   g_gstart[NG + 1];
__device__ float g_hg[NG * 3 * H];

// ---------------- convert x -> bf16 and W1/2/3 -> transposed bf16 ----------------
#define CONV_XBLOCKS ((N_NODES * H) / 1024)   // 6250
__global__ void k_conv(const float* __restrict__ x, const float* __restrict__ W1,
                       const float* __restrict__ W2, const float* __restrict__ W3) {
    int b = blockIdx.x;
    if (b < CONV_XBLOCKS) {
        int i = (b * 256 + threadIdx.x) * 4;
        float4 v = *(const float4*)(x + i);
        __nv_bfloat162 p0 = __floats2bfloat162_rn(v.x, v.y);
        __nv_bfloat162 p1 = __floats2bfloat162_rn(v.z, v.w);
        uint2 u; u.x = *(uint32_t*)&p0; u.y = *(uint32_t*)&p1;
        *(uint2*)&g_xbf[i] = u;
    } else {
        int idx = ((b - CONV_XBLOCKS) * 256 + threadIdx.x) * 4;
        if (idx < 3 * H * H) {
            int l = idx >> 14;
            int rem = idx & (H * H - 1);
            int n = rem >> 7, k = rem & 127;
            const float* Wsrc = (l == 0) ? W1 : (l == 1) ? W2 : W3;
            float f0 = Wsrc[(k + 0) * H + n];
            float f1 = Wsrc[(k + 1) * H + n];
            float f2 = Wsrc[(k + 2) * H + n];
            float f3 = Wsrc[(k + 3) * H + n];
            __nv_bfloat162 p0 = __floats2bfloat162_rn(f0, f1);
            __nv_bfloat162 p1 = __floats2bfloat162_rn(f2, f3);
            uint2 u; u.x = *(uint32_t*)&p0; u.y = *(uint32_t*)&p1;
            *(uint2*)&g_Wt[idx] = u;
        }
    }
}

// ---------------- init: zero counts + hg, graph segment starts ----------------
__global__ void k_init(const int* __restrict__ gid) {
    int i = blockIdx.x * blockDim.x + threadIdx.x;
    if (i < NP1) g_rowptr[i] = 0;
    if (i < NG * 3 * H) g_hg[i] = 0.f;
    if (i < N_NODES) {
        int gi = gid[i];
        int gp = (i == 0) ? -1 : gid[i - 1];
        for (int g = gp + 1; g <= gi; g++) g_gstart[g] = i;
        if (i == N_NODES - 1)
            for (int g = gi + 1; g <= NG; g++) g_gstart[g] = N_NODES;
    }
}

__global__ void k_hist(const int* __restrict__ dst) {
    int e = blockIdx.x * blockDim.x + threadIdx.x;
    if (e < N_EDGES) atomicAdd(&g_rowptr[dst[e] + 1], 1);
}

// ---------------- scan phase 1: block-local inclusive ----------------
__global__ void k_scan1() {
    __shared__ int wsum[32];
    int tid = threadIdx.x, lane = tid & 31, wid = tid >> 5;
    int i = blockIdx.x * 1024 + tid;
    int x = (i < NP1) ? g_rowptr[i] : 0;
#pragma unroll
    for (int off = 1; off < 32; off <<= 1) {
        int t = __shfl_up_sync(FULLMASK, x, off);
        if (lane >= off) x += t;
    }
    if (lane == 31) wsum[wid] = x;
    __syncthreads();
    if (wid == 0) {
        int y = wsum[lane];
#pragma unroll
        for (int off = 1; off < 32; off <<= 1) {
            int t = __shfl_up_sync(FULLMASK, y, off);
            if (lane >= off) y += t;
        }
        wsum[lane] = y;
    }
    __syncthreads();
    int v = x + (wid ? wsum[wid - 1] : 0);
    if (i < NP1) g_rowptr[i] = v;
    if (tid == 1023) g_bsum[blockIdx.x] = v;
}

// ---------------- scan phase 2 (fused, parallel): add block offsets + cursor ----------------
__global__ void k_scan3() {
    __shared__ int warpsum[2];
    int b = blockIdx.x;
    int lim = b >> 2;
    int tid = threadIdx.x;
    int v = 0;
    if (tid < lim) v = g_bsum[tid];
    if (tid < 64) {
#pragma unroll
        for (int off = 16; off >= 1; off >>= 1)
            v += __shfl_xor_sync(FULLMASK, v, off);
        if ((tid & 31) == 0) warpsum[tid >> 5] = v;
    }
    __syncthreads();
    int soff = warpsum[0] + warpsum[1];
    int i = b * 256 + tid;
    if (i < NP1) {
        int vv = g_rowptr[i] + soff;
        g_rowptr[i] = vv;
        if (i < N_NODES) g_cursor[i] = vv;
    }
}

// ---------------- scatter: CSR src + per-layer edge projections ----------------
__global__ void k_scatter(const int* __restrict__ src, const int* __restrict__ dst,
                          const float* __restrict__ e_feat,
                          const float* __restrict__ a1, const float* __restrict__ a2,
                          const float* __restrict__ a3) {
    int e = blockIdx.x * blockDim.x + threadIdx.x;
    if (e >= N_EDGES) return;
    int d = dst[e];
    int p = atomicAdd(&g_cursor[d], 1);
    g_csr_src[p] = src[e];
    const float* ef = e_feat + (size_t)e * ED;
    float p1 = 0.f, p2 = 0.f, p3 = 0.f;
#pragma unroll
    for (int i = 0; i < 4; i++) {
        float4 f = *(const float4*)(ef + i * 4);
        float4 u = *(const float4*)(a1 + 2 * H + i * 4);
        float4 v = *(const float4*)(a2 + 2 * H + i * 4);
        float4 w = *(const float4*)(a3 + 2 * H + i * 4);
        p1 += f.x * u.x + f.y * u.y + f.z * u.z + f.w * u.w;
        p2 += f.x * v.x + f.y * v.y + f.z * v.z + f.w * v.w;
        p3 += f.x * w.x + f.y * w.y + f.z * w.z + f.w * w.w;
    }
    g_eproj[0][p] = p1;
    g_eproj[1][p] = p2;
    g_eproj[2][p] = p3;
}

// ---------------- pipelined bf16 GEMM + fused attention-score epilogue ----------------
__device__ __forceinline__ void mma_bf16(float* c, const uint32_t* a, const uint32_t* b) {
    asm volatile(
        "mma.sync.aligned.m16n8k16.row.col.f32.bf16.bf16.f32 "
        "{%0,%1,%2,%3}, {%4,%5,%6,%7}, {%8,%9}, {%0,%1,%2,%3};"
        : "+f"(c[0]), "+f"(c[1]), "+f"(c[2]), "+f"(c[3])
        : "r"(a[0]), "r"(a[1]), "r"(a[2]), "r"(a[3]), "r"(b[0]), "r"(b[1]));
}
__device__ __forceinline__ void cp16(uint32_t dst, const void* src, bool full) {
    int sz = full ? 16 : 0;
    asm volatile("cp.async.cg.shared.global [%0], [%1], 16, %2;\n"
                 :: "r"(dst), "l"(src), "r"(sz));
}

#define BSTRIDE 40
#define ATILE (128 * BSTRIDE)
#define WTILE (128 * BSTRIDE)
#define GEMM_SMEM ((4 * ATILE) * 2 + 256 * 4)   // ~42 KB

__global__ void __launch_bounds__(256, 2)
k_gemm_tc(const __nv_bfloat16* __restrict__ A, const __nv_bfloat16* __restrict__ Wt,
          const float* __restrict__ avec, __nv_bfloat16* __restrict__ Zbf, int nrows) {
    extern __shared__ __nv_bfloat16 smb[];
    __nv_bfloat16* As = smb;                    // [2][128][40]
    __nv_bfloat16* Ws = smb + 2 * ATILE;        // [2][128][40]
    float* red = (float*)(smb + 4 * ATILE);     // [128][2]

    int tid = threadIdx.x;
    int wid = tid >> 5, lane = tid & 31;
    int gId = lane >> 2, tig = lane & 3;
    int m0 = blockIdx.x * 128;
    int wm = (wid >> 1) * 32;
    int wn = (wid & 1) * 64;

    uint32_t sA = (uint32_t)__cvta_generic_to_shared(As);
    uint32_t sW = (uint32_t)__cvta_generic_to_shared(Ws);

    if (tid < 128) { red[tid * 2] = 0.f; red[tid * 2 + 1] = 0.f; }

    float acc[2][8][4];
#pragma unroll
    for (int i = 0; i < 2; i++)
#pragma unroll
        for (int j = 0; j < 8; j++)
#pragma unroll
            for (int k = 0; k < 4; k++) acc[i][j][k] = 0.f;

    auto load_stage = [&](int kt, int buf) {
#pragma unroll
        for (int p = 0; p < 2; p++) {
            int idx = p * 256 + tid;
            int m  = idx >> 2;
            int c8 = (idx & 3) * 8;
            bool v = (m0 + m) < nrows;
            cp16(sA + (uint32_t)(buf * ATILE + m * BSTRIDE + c8) * 2,
                 A + (size_t)(v ? (m0 + m) : 0) * H + kt + c8, v);
        }
#pragma unroll
        for (int p = 0; p < 2; p++) {
            int idx = p * 256 + tid;
            int n  = idx >> 2;
            int c8 = (idx & 3) * 8;
            cp16(sW + (uint32_t)(buf * WTILE + n * BSTRIDE + c8) * 2,
                 Wt + (size_t)n * H + kt + c8, true);
        }
        asm volatile("cp.async.commit_group;\n");
    };

    load_stage(0, 0);

#pragma unroll
    for (int t = 0; t < 4; t++) {
        if (t < 3) {
            load_stage((t + 1) * 32, (t + 1) & 1);
            asm volatile("cp.async.wait_group 1;\n");
        } else {
            asm volatile("cp.async.wait_group 0;\n");
        }
        __syncthreads();
        int buf = t & 1;
        const __nv_bfloat16* Ab = As + buf * ATILE;
        const __nv_bfloat16* Wb = Ws + buf * WTILE;
#pragma unroll
        for (int ks = 0; ks < 32; ks += 16) {
            uint32_t a[2][4], b[8][2];
#pragma unroll
            for (int mi = 0; mi < 2; mi++) {
                int r = wm + mi * 16;
                a[mi][0] = *(const uint32_t*)&Ab[(r + gId) * BSTRIDE + ks + 2 * tig];
                a[mi][1] = *(const uint32_t*)&Ab[(r + gId + 8) * BSTRIDE + ks + 2 * tig];
                a[mi][2] = *(const uint32_t*)&Ab[(r + gId) * BSTRIDE + ks + 2 * tig + 8];
                a[mi][3] = *(const uint32_t*)&Ab[(r + gId + 8) * BSTRIDE + ks + 2 * tig + 8];
            }
#pragma unroll
            for (int ni = 0; ni < 8; ni++) {
                int n = wn + ni * 8 + gId;
                b[ni][0] = *(const uint32_t*)&Wb[n * BSTRIDE + ks + 2 * tig];
                b[ni][1] = *(const uint32_t*)&Wb[n * BSTRIDE + ks + 2 * tig + 8];
            }
#pragma unroll
            for (int mi = 0; mi < 2; mi++)
#pragma unroll
                for (int ni = 0; ni < 8; ni++)
                    mma_bf16(acc[mi][ni], a[mi], b[ni]);
        }
        __syncthreads();
    }

    // epilogue: bf16 z store + attention-score partial dots (fp32)
#pragma unroll
    for (int mi = 0; mi < 2; mi++) {
        float ps0 = 0.f, pd0 = 0.f, ps1 = 0.f, pd1 = 0.f;
        int rl = wm + mi * 16 + gId;
        int r0 = m0 + rl;
#pragma unroll
        for (int ni = 0; ni < 8; ni++) {
            int c = wn + ni * 8 + tig * 2;
            float a0s = avec[c], a1s = avec[c + 1];
            float a0d = avec[H + c], a1d = avec[H + c + 1];
            ps0 += acc[mi][ni][0] * a0s + acc[mi][ni][1] * a1s;
            pd0 += acc[mi][ni][0] * a0d + acc[mi][ni][1] * a1d;
            ps1 += acc[mi][ni][2] * a0s + acc[mi][ni][3] * a1s;
            pd1 += acc[mi][ni][2] * a0d + acc[mi][ni][3] * a1d;
            if (r0 < nrows) {
                __nv_bfloat162 p = __floats2bfloat162_rn(acc[mi][ni][0], acc[mi][ni][1]);
                *(uint32_t*)&Zbf[(size_t)r0 * H + c] = *(uint32_t*)&p;
            }
            if (r0 + 8 < nrows) {
                __nv_bfloat162 p = __floats2bfloat162_rn(acc[mi][ni][2], acc[mi][ni][3]);
                *(uint32_t*)&Zbf[(size_t)(r0 + 8) * H + c] = *(uint32_t*)&p;
            }
        }
        atomicAdd(&red[rl * 2],     ps0);
        atomicAdd(&red[rl * 2 + 1], pd0);
        atomicAdd(&red[(rl + 8) * 2],     ps1);
        atomicAdd(&red[(rl + 8) * 2 + 1], pd1);
    }
    __syncthreads();
    if (tid < 128 && m0 + tid < nrows) {
        g_ssrc[m0 + tid] = red[tid * 2];
        g_sdst[m0 + tid] = red[tid * 2 + 1];
    }
}

// ---------------- warp-per-node softmax + aggregation: 2 edges/iter, 16 lanes each ----------------
__global__ void k_aggregate(const float* __restrict__ eproj, float* __restrict__ h_out,
                            __nv_bfloat16* __restrict__ hbf,
                            const float* __restrict__ w_att, const float* __restrict__ b_att) {
    int t = blockIdx.x * blockDim.x + threadIdx.x;
    int w = t >> 5, lane = t & 31;
    if (w >= N_NODES) return;
    int half = lane >> 4;     // 0: even edges, 1: odd edges
    int lh = lane & 15;       // covers cols lh*8 .. lh*8+7
    int s0 = g_rowptr[w], s1 = g_rowptr[w + 1];
    float sd = g_sdst[w];

    float acc[8];
#pragma unroll
    for (int i = 0; i < 8; i++) acc[i] = 0.f;
    float ssum = 0.f;

    for (int base = s0; base < s1; base += 32) {
        int e = base + lane;
        float ex = 0.f;
        int sj = 0;
        if (e < s1) {
            sj = g_csr_src[e];
            float tt = g_ssrc[sj] + sd + eproj[e];
            tt = (tt >= 0.f) ? tt : 0.2f * tt;
            ex = __expf(tt);
        }
        ssum += ex;
        int cnt = min(32, s1 - base);
        int pairs = (cnt + 1) >> 1;
#pragma unroll 4
        for (int j = 0; j < pairs; j++) {
            int idx = (j << 1) | half;               // edge handled by this half-warp
            float exj = __shfl_sync(FULLMASK, ex, idx);   // 0 for idx beyond cnt
            int   srj = __shfl_sync(FULLMASK, sj, idx);   // 0 (safe row) beyond cnt
            uint4 u = *(const uint4*)&g_zbf[(size_t)srj * H + lh * 8];
            acc[0] += exj * __uint_as_float(u.x << 16);
            acc[1] += exj * __uint_as_float(u.x & 0xffff0000u);
            acc[2] += exj * __uint_as_float(u.y << 16);
            acc[3] += exj * __uint_as_float(u.y & 0xffff0000u);
            acc[4] += exj * __uint_as_float(u.z << 16);
            acc[5] += exj * __uint_as_float(u.z & 0xffff0000u);
            acc[6] += exj * __uint_as_float(u.w << 16);
            acc[7] += exj * __uint_as_float(u.w & 0xffff0000u);
        }
    }
#pragma unroll
    for (int off = 16; off >= 1; off >>= 1)
        ssum += __shfl_xor_sync(FULLMASK, ssum, off);
    float inv = (ssum > 0.f) ? 1.f / ssum : 0.f;

    // combine the two edge-halves: lanes L and L+16 hold partial sums of same cols
#pragma unroll
    for (int i = 0; i < 8; i++) {
        acc[i] += __shfl_xor_sync(FULLMASK, acc[i], 16);
        acc[i] = fmaxf(acc[i] * inv, 0.f);        // relu(h)
    }

    if (half == 0) {
        float4 o0 = make_float4(acc[0], acc[1], acc[2], acc[3]);
        float4 o1 = make_float4(acc[4], acc[5], acc[6], acc[7]);
        *(float4*)&h_out[(size_t)w * H + lh * 8]     = o0;
        *(float4*)&h_out[(size_t)w * H + lh * 8 + 4] = o1;
        if (hbf) {
            __nv_bfloat162 p0 = __floats2bfloat162_rn(acc[0], acc[1]);
            __nv_bfloat162 p1 = __floats2bfloat162_rn(acc[2], acc[3]);
            __nv_bfloat162 p2 = __floats2bfloat162_rn(acc[4], acc[5]);
            __nv_bfloat162 p3 = __floats2bfloat162_rn(acc[6], acc[7]);
            uint4 u;
            u.x = *(uint32_t*)&p0; u.y = *(uint32_t*)&p1;
            u.z = *(uint32_t*)&p2; u.w = *(uint32_t*)&p3;
            *(uint4*)&hbf[(size_t)w * H + lh * 8] = u;
        }
    }

    // fused readout attention score (all lanes have identical acc after xor-16)
    float p = 0.f;
#pragma unroll
    for (int i = 0; i < 8; i++)
        p += acc[i] * w_att[lh * 8 + i];
#pragma unroll
    for (int off = 8; off >= 1; off >>= 1)
        p += __shfl_xor_sync(FULLMASK, p, off);
    if (lane == 0) {
        float tt = p + b_att[0];
        tt = (tt >= 0.f) ? tt : 0.01f * tt;
        g_att[w] = __expf(tt);
    }
}

// ---------------- per-graph readout (4-way split, atomic numerators) ----------------
__global__ void k_readout(const float* __restrict__ hsrc, int layer_off) {
    int g = blockIdx.x;
    int q = blockIdx.y;
    int c = threadIdx.x;
    int s = g_gstart[g], e = g_gstart[g + 1];
    float a0 = 0.f;
    for (int i = s + q; i < e; i += 4)
        a0 += g_att[i] * hsrc[(size_t)i * H + c];
    atomicAdd(&g_hg[g * (3 * H) + layer_off + c], a0);
}

// ---------------- classifier + log_softmax ----------------
__global__ void k_cls(const float* __restrict__ Wcls, const float* __restrict__ bcls,
                      float* __restrict__ out) {
    int t = blockIdx.x * blockDim.x + threadIdx.x;
    int w = t >> 5, lane = t & 31;
    if (w >= NG) return;
    int cnt = g_gstart[w + 1] - g_gstart[w];
    float invden = 1.f / (float)(cnt > 1 ? cnt : 1);
    float y = -INFINITY;
    if (lane < NC) {
        float acc = 0.f;
        const float* hgp = &g_hg[w * 3 * H];
#pragma unroll 8
        for (int k = 0; k < 3 * H; k++)
            acc += hgp[k] * Wcls[k * NC + lane];
        y = acc * invden + bcls[lane];
    }
    float mx = y;
#pragma unroll
    for (int off = 16; off >= 1; off >>= 1)
        mx = fmaxf(mx, __shfl_xor_sync(FULLMASK, mx, off));
    float ex = (lane < NC) ? __expf(y - mx) : 0.f;
    float sm = ex;
#pragma unroll
    for (int off = 16; off >= 1; off >>= 1)
        sm += __shfl_xor_sync(FULLMASK, sm, off);
    if (lane < NC) out[w * NC + lane] = (y - mx) - logf(sm);
}

// ---------------- host orchestration ----------------
static cudaStream_t s2 = nullptr;
static cudaEvent_t evFork, evG1, evA1, evR1, evA2, evR2;

extern "C" void kernel_launch(void* const* d_in, const int* in_sizes, int n_in,
                              void* d_out, int out_size) {
    const float* x      = (const float*)d_in[0];
    const float* e_feat = (const float*)d_in[1];
    const int*   src    = (const int*)d_in[2];
    const int*   dst    = (const int*)d_in[3];
    const int*   gid    = (const int*)d_in[4];
    const float* W1 = (const float*)d_in[5];
    const float* a1 = (const float*)d_in[6];
    const float* W2 = (const float*)d_in[7];
    const float* a2 = (const float*)d_in[8];
    const float* W3 = (const float*)d_in[9];
    const float* a3 = (const float*)d_in[10];
    const float* w_att = (const float*)d_in[11];
    const float* b_att = (const float*)d_in[12];
    const float* Wcls  = (const float*)d_in[13];
    const float* bcls  = (const float*)d_in[14];
    float* out = (float*)d_out;

    if (s2 == nullptr) {
        cudaStreamCreateWithFlags(&s2, cudaStreamNonBlocking);
        cudaEventCreateWithFlags(&evFork, cudaEventDisableTiming);
        cudaEventCreateWithFlags(&evG1,  cudaEventDisableTiming);
        cudaEventCreateWithFlags(&evA1,  cudaEventDisableTiming);
        cudaEventCreateWithFlags(&evR1,  cudaEventDisableTiming);
        cudaEventCreateWithFlags(&evA2,  cudaEventDisableTiming);
        cudaEventCreateWithFlags(&evR2,  cudaEventDisableTiming);
        cudaFuncSetAttribute(k_gemm_tc, cudaFuncAttributeMaxDynamicSharedMemorySize, GEMM_SMEM);
    }

    float *p_hA, *p_hB, *p_ep;
    __nv_bfloat16 *p_zbf, *p_xbf, *p_hbfA, *p_hbfB, *p_Wt;
    cudaGetSymbolAddress((void**)&p_zbf,  g_zbf);
    cudaGetSymbolAddress((void**)&p_hA,   g_hA);
    cudaGetSymbolAddress((void**)&p_hB,   g_hB);
    cudaGetSymbolAddress((void**)&p_ep,   g_eproj);
    cudaGetSymbolAddress((void**)&p_xbf,  g_xbf);
    cudaGetSymbolAddress((void**)&p_hbfA, g_hbfA);
    cudaGetSymbolAddress((void**)&p_hbfB, g_hbfB);
    cudaGetSymbolAddress((void**)&p_Wt,   g_Wt);

    int wb = (N_NODES * 32 + 255) / 256;
    int gb = (N_NODES + 127) / 128;
    dim3 rgrid(NG, 4);

    cudaEventRecord(evFork, 0);
    cudaStreamWaitEvent(s2, evFork, 0);

    k_conv<<<CONV_XBLOCKS + 48, 256, 0, s2>>>(x, W1, W2, W3);                 // #1
    k_init<<<(NP1 + 255) / 256, 256>>>(gid);                                  // #2
    k_hist<<<(N_EDGES + 255) / 256, 256>>>(dst);                              // #3
    k_gemm_tc<<<gb, 256, GEMM_SMEM, s2>>>(p_xbf, p_Wt, a1, p_zbf, N_NODES);   // #4
    cudaEventRecord(evG1, s2);
    k_scan1<<<SCAN_BLOCKS, 1024>>>();                                         // #5
    k_scan3<<<(NP1 + 255) / 256, 256>>>();                                    // #6
    k_scatter<<<(N_EDGES + 255) / 256, 256>>>(src, dst, e_feat, a1, a2, a3);  // #7

    // layer 1
    cudaStreamWaitEvent(0, evG1, 0);
    k_aggregate<<<wb, 256>>>(p_ep + 0 * N_EDGES, p_hA, p_hbfA, w_att, b_att);
    cudaEventRecord(evA1, 0);
    cudaStreamWaitEvent(s2, evA1, 0);
    k_readout<<<rgrid, 128, 0, s2>>>(p_hA, 0);
    cudaEventRecord(evR1, s2);

    // layer 2 (overlaps readout-1)
    k_gemm_tc<<<gb, 256, GEMM_SMEM>>>(p_hbfA, p_Wt + H * H, a2, p_zbf, N_NODES);
    k_aggregate<<<wb, 256>>>(p_ep + 1 * N_EDGES, p_hB, p_hbfB, w_att, b_att);
    cudaEventRecord(evA2, 0);
    cudaStreamWaitEvent(s2, evA2, 0);
    k_readout<<<rgrid, 128, 0, s2>>>(p_hB, H);
    cudaEventRecord(evR2, s2);

    // layer 3 (overlaps readout-2)
    k_gemm_tc<<<gb, 256, GEMM_SMEM>>>(p_hbfB, p_Wt + 2 * H * H, a3, p_zbf, N_NODES);
    k_aggregate<<<wb, 256>>>(p_ep + 2 * N_EDGES, p_hA, (__nv_bfloat16*)nullptr, w_att, b_att);
    k_readout<<<rgrid, 128>>>(p_hA, 2 * H);

    cudaStreamWaitEvent(0, evR1, 0);
    cudaStreamWaitEvent(0, evR2, 0);
    k_cls<<<2, 1024>>>(Wcls, bcls, out);
}